// round 11
// baseline (speedup 1.0000x reference)
#include <cuda_runtime.h>
#include <cstdint>

// Aggregator: masked mean of sampled neighbor features.
//  d_in[0] features:      [N, 128] float32
//  d_in[1] neighbor_idx:  [N, 16]  int32
//  d_in[2] neighbor_mask: [N, 16]  int32 (0/1)
//  d_out   out:           [N, 128] float32
//
// One warp per node. Row split into 4 chunks of 32 floats; lane l loads
// col 32c+l of chunk c -> every load is a single-line (128B) LDG.32,
// avoiding the ~2x within-LDG wavefront replay cost of LDG.128, and each
// outstanding load costs 1 register -> much higher MLP at same occupancy.
// Lane l owns cols {l, 32+l, 64+l, 96+l}; output stored as 4x STG.32.

#define S 16
#define D 128

__global__ __launch_bounds__(256) void agg_kernel(
    const float* __restrict__ feat,
    const int* __restrict__ nidx,
    const int* __restrict__ mask,
    float* __restrict__ out,
    int n)
{
    int warp = (int)((blockIdx.x * (unsigned)blockDim.x + threadIdx.x) >> 5);
    int lane = threadIdx.x & 31;
    if (warp >= n) return;

    // ---- 16 int32 mask values as 4x int4 (uniform across warp) ----
    const int4* mp = reinterpret_cast<const int4*>(mask + (size_t)warp * S);
    unsigned nz = 0;
#pragma unroll
    for (int q = 0; q < 4; q++) {
        int4 m = __ldg(mp + q);
        nz |= (unsigned)(m.x != 0) << (4 * q + 0);
        nz |= (unsigned)(m.y != 0) << (4 * q + 1);
        nz |= (unsigned)(m.z != 0) << (4 * q + 2);
        nz |= (unsigned)(m.w != 0) << (4 * q + 3);
    }
    int cnt = __popc(nz);

    // ---- 16 int32 indices as 4x int4 (uniform across warp) ----
    const int4* ip = reinterpret_cast<const int4*>(nidx + (size_t)warp * S);
    int idx[S];
#pragma unroll
    for (int q = 0; q < 4; q++) {
        int4 v = __ldg(ip + q);
        idx[4 * q + 0] = v.x; idx[4 * q + 1] = v.y;
        idx[4 * q + 2] = v.z; idx[4 * q + 3] = v.w;
    }

    // ---- flat predicated gather-accumulate: 4 single-line LDG.32 per row ----
    float a0 = 0.f, a1 = 0.f, a2 = 0.f, a3 = 0.f;
#pragma unroll
    for (int j = 0; j < S; j++) {
        if ((nz >> j) & 1u) {
            const float* row = feat + (size_t)idx[j] * D + lane;  // one base reg
            float v0 = __ldg(row + 0);     // cols [0,32):  1 line / warp
            float v1 = __ldg(row + 32);    // cols [32,64)
            float v2 = __ldg(row + 64);    // cols [64,96)
            float v3 = __ldg(row + 96);    // cols [96,128)
            a0 += v0; a1 += v1; a2 += v2; a3 += v3;
        }
    }

    // ---- scale by 1/count and store as 4 single-line STG.32 ----
    float inv = 1.0f / (float)(cnt > 0 ? cnt : 1);
    float* o = out + (size_t)warp * D + lane;
    o[0]  = a0 * inv;
    o[32] = a1 * inv;
    o[64] = a2 * inv;
    o[96] = a3 * inv;
}

extern "C" void kernel_launch(void* const* d_in, const int* in_sizes, int n_in,
                              void* d_out, int out_size)
{
    const float* feat = (const float*)d_in[0];
    const int*   nidx = (const int*)d_in[1];
    const int*   mask = (const int*)d_in[2];
    float*       out  = (float*)d_out;

    int n = in_sizes[1] / S;              // 100000 nodes
    int warps_per_block = 256 / 32;       // 8 warps/block
    int blocks = (n + warps_per_block - 1) / warps_per_block;
    agg_kernel<<<blocks, 256>>>(feat, nidx, mask, out, n);
}

// round 12
// speedup vs baseline: 1.1005x; 1.1005x over previous
#include <cuda_runtime.h>
#include <cstdint>

// Aggregator: masked mean of sampled neighbor features.
//  d_in[0] features:      [N, 128] float32
//  d_in[1] neighbor_idx:  [N, 16]  int32
//  d_in[2] neighbor_mask: [N, 16]  int32 (0/1)
//  d_out   out:           [N, 128] float32
//
// R10 structure (47.5us) with ONE delta: gathers use LDG.128.CG (no L1
// allocate -> no miss-fill double-handling on the L1 datapath; table rows
// have ~0 L1 hit rate so caching them is pure overhead) and the write-once
// output uses STG.CG. One warp per node; lane l owns float4 cols [4l,4l+4);
// flat fully-unrolled predicated gather loop; packed f32x2 accumulation.

#define S 16
#define D 128

__device__ __forceinline__ unsigned long long addx2(unsigned long long a, unsigned long long b) {
    unsigned long long r;
    asm("add.rn.f32x2 %0, %1, %2;" : "=l"(r) : "l"(a), "l"(b));
    return r;
}

__global__ __launch_bounds__(256) void agg_kernel(
    const float* __restrict__ feat,
    const int* __restrict__ nidx,
    const int* __restrict__ mask,
    float* __restrict__ out,
    int n)
{
    int warp = (int)((blockIdx.x * (unsigned)blockDim.x + threadIdx.x) >> 5);
    int lane = threadIdx.x & 31;
    if (warp >= n) return;

    // ---- 16 int32 mask values as 4x int4 (uniform across warp) ----
    const int4* mp = reinterpret_cast<const int4*>(mask + (size_t)warp * S);
    unsigned nz = 0;
#pragma unroll
    for (int q = 0; q < 4; q++) {
        int4 m = __ldg(mp + q);
        nz |= (unsigned)(m.x != 0) << (4 * q + 0);
        nz |= (unsigned)(m.y != 0) << (4 * q + 1);
        nz |= (unsigned)(m.z != 0) << (4 * q + 2);
        nz |= (unsigned)(m.w != 0) << (4 * q + 3);
    }
    int cnt = __popc(nz);

    // ---- 16 int32 indices as 4x int4 (uniform across warp) ----
    const int4* ip = reinterpret_cast<const int4*>(nidx + (size_t)warp * S);
    int idx[S];
#pragma unroll
    for (int q = 0; q < 4; q++) {
        int4 v = __ldg(ip + q);
        idx[4 * q + 0] = v.x; idx[4 * q + 1] = v.y;
        idx[4 * q + 2] = v.z; idx[4 * q + 3] = v.w;
    }

    // ---- flat predicated gather-accumulate: LDG.128.CG, packed f32x2 ----
    unsigned long long aLo = 0ull, aHi = 0ull;     // bitwise 0 == (0.f, 0.f)
#pragma unroll
    for (int j = 0; j < S; j++) {
        if ((nz >> j) & 1u) {
            const float4* row =
                reinterpret_cast<const float4*>(feat + (size_t)idx[j] * D) + lane;
            float4 v = __ldcg(row);                 // no L1 allocate
            unsigned long long lo, hi;
            asm("mov.b64 %0, {%1, %2};" : "=l"(lo) : "f"(v.x), "f"(v.y));
            asm("mov.b64 %0, {%1, %2};" : "=l"(hi) : "f"(v.z), "f"(v.w));
            aLo = addx2(aLo, lo);
            aHi = addx2(aHi, hi);
        }
    }

    // ---- scale by 1/count and store (write-once, no L1 allocate) ----
    float inv = 1.0f / (float)(cnt > 0 ? cnt : 1);
    float x, y, z, w;
    asm("mov.b64 {%0, %1}, %2;" : "=f"(x), "=f"(y) : "l"(aLo));
    asm("mov.b64 {%0, %1}, %2;" : "=f"(z), "=f"(w) : "l"(aHi));
    float4 r = make_float4(x * inv, y * inv, z * inv, w * inv);
    __stcg(reinterpret_cast<float4*>(out) + (size_t)warp * (D / 4) + lane, r);
}

extern "C" void kernel_launch(void* const* d_in, const int* in_sizes, int n_in,
                              void* d_out, int out_size)
{
    const float* feat = (const float*)d_in[0];
    const int*   nidx = (const int*)d_in[1];
    const int*   mask = (const int*)d_in[2];
    float*       out  = (float*)d_out;

    int n = in_sizes[1] / S;              // 100000 nodes
    int warps_per_block = 256 / 32;       // 8 warps/block
    int blocks = (n + warps_per_block - 1) / warps_per_block;
    agg_kernel<<<blocks, 256>>>(feat, nidx, mask, out, n);
}